// round 6
// baseline (speedup 1.0000x reference)
#include <cuda_runtime.h>
#include <math.h>
#include <math_constants.h>
#include <stdint.h>

#define NT 4096
#define DM 1024
#define DF 2048
#define NE 8
#define MAXROWS (2*NT)
#define MAXTILES 80
#define TILEY 72

// ---------------- static device scratch ----------------
__device__ int   g_counts[NE];
__device__ int   g_cursor[NE];
__device__ int   g_offsets[NE+1];
__device__ int   g_perm[MAXROWS];
__device__ float g_rowgate[MAXROWS];
__device__ int   g_slot[MAXROWS];
__device__ int   g_topidx[MAXROWS];
__device__ float g_gatesv[MAXROWS];
__device__ float g_imp_part[NE*NT];
__device__ float g_load_part[NE*NT];
__device__ float g_impsum[NE];
__device__ float g_loadsum[NE];
__device__ int   g_tile_e[MAXTILES];
__device__ int   g_tile_r0[MAXTILES];
__device__ int   g_tile_r1[MAXTILES];
__device__ int   g_ntiles;
__device__ float g_H[(size_t)MAXROWS * DF];        // K-permuted tf32 activations
__device__ float g_O[(size_t)MAXROWS * DM];        // natural layout
__device__ float g_Xr[(size_t)NT * DM];            // K-permuted tf32 x

// ---------------- helpers ----------------
__device__ __forceinline__ uint32_t smem_u32(const void* p) {
    uint32_t r;
    asm("{ .reg .u64 t; cvta.to.shared.u64 t, %1; cvt.u32.u64 %0, t; }" : "=r"(r) : "l"(p));
    return r;
}
__device__ __forceinline__ float rna_tf32(float v) {
    uint32_t u;
    asm("cvt.rna.tf32.f32 %0, %1;" : "=r"(u) : "f"(v));
    return __uint_as_float(u);
}
__device__ __forceinline__ uint32_t rna_tf32_u(float v) {
    uint32_t u;
    asm("cvt.rna.tf32.f32 %0, %1;" : "=r"(u) : "f"(v));
    return u;
}
// within each 8-group, store K order [0,4,1,5,2,6,3,7]; fragment pairs (k, k+4) contiguous
__device__ __forceinline__ int permk(int k) {
    int j = k & 7;
    return (k & ~7) + ((j < 4) ? 2*j : 2*(j-4) + 1);
}
__device__ __forceinline__ void mma_tf32(float* c, uint32_t a0, uint32_t a1,
                                         uint32_t a2, uint32_t a3,
                                         uint32_t b0, uint32_t b1) {
    asm volatile("mma.sync.aligned.m16n8k8.row.col.f32.tf32.tf32.f32 "
        "{%0,%1,%2,%3}, {%4,%5,%6,%7}, {%8,%9}, {%0,%1,%2,%3};"
        : "+f"(c[0]), "+f"(c[1]), "+f"(c[2]), "+f"(c[3])
        : "r"(a0), "r"(a1), "r"(a2), "r"(a3), "r"(b0), "r"(b1));
}

// ---------------- reset ----------------
__global__ void reset_kernel() {
    int i = threadIdx.x;
    if (i < NE) { g_counts[i] = 0; g_cursor[i] = 0; }
}

// ---------------- gating: one warp per token; also emits K-permuted tf32 x ----------------
__global__ void gating_kernel(const float* __restrict__ x,
                              const float* __restrict__ noise,
                              const float* __restrict__ wg,
                              const float* __restrict__ wn)
{
    int warp = (blockIdx.x * blockDim.x + threadIdx.x) >> 5;
    int lane = threadIdx.x & 31;
    if (warp >= NT) return;
    const int t = warp;

    float cg[NE], ng[NE];
    #pragma unroll
    for (int e = 0; e < NE; e++) { cg[e] = 0.f; ng[e] = 0.f; }

    const float* xr = x + (size_t)t * DM;
    float* xo = g_Xr + (size_t)t * DM;
    for (int k = lane; k < DM; k += 32) {
        float xv = xr[k];
        xo[permk(k)] = rna_tf32(xv);
        const float4* wg4 = (const float4*)(wg + (size_t)k * NE);
        const float4* wn4 = (const float4*)(wn + (size_t)k * NE);
        float4 a = wg4[0], b = wg4[1];
        float4 c = wn4[0], d = wn4[1];
        cg[0] = fmaf(xv, a.x, cg[0]); cg[1] = fmaf(xv, a.y, cg[1]);
        cg[2] = fmaf(xv, a.z, cg[2]); cg[3] = fmaf(xv, a.w, cg[3]);
        cg[4] = fmaf(xv, b.x, cg[4]); cg[5] = fmaf(xv, b.y, cg[5]);
        cg[6] = fmaf(xv, b.z, cg[6]); cg[7] = fmaf(xv, b.w, cg[7]);
        ng[0] = fmaf(xv, c.x, ng[0]); ng[1] = fmaf(xv, c.y, ng[1]);
        ng[2] = fmaf(xv, c.z, ng[2]); ng[3] = fmaf(xv, c.w, ng[3]);
        ng[4] = fmaf(xv, d.x, ng[4]); ng[5] = fmaf(xv, d.y, ng[5]);
        ng[6] = fmaf(xv, d.z, ng[6]); ng[7] = fmaf(xv, d.w, ng[7]);
    }
    #pragma unroll
    for (int e = 0; e < NE; e++) {
        #pragma unroll
        for (int o = 16; o > 0; o >>= 1) {
            cg[e] += __shfl_xor_sync(0xFFFFFFFFu, cg[e], o);
            ng[e] += __shfl_xor_sync(0xFFFFFFFFu, ng[e], o);
        }
    }

    if (lane == 0) {
        float clean[NE], stdv[NE], noisy[NE];
        #pragma unroll
        for (int e = 0; e < NE; e++) {
            clean[e] = cg[e];
            float v = ng[e];
            float sp = fmaxf(v, 0.f) + log1pf(expf(-fabsf(v)));
            stdv[e]  = sp + 0.01f;
            noisy[e] = clean[e] + noise[(size_t)t * NE + e] * stdv[e];
        }
        int i0 = 0, i1 = -1;
        float v0 = -CUDART_INF_F, v1 = -CUDART_INF_F, v2 = -CUDART_INF_F;
        #pragma unroll
        for (int e = 0; e < NE; e++) if (noisy[e] > v0) { v0 = noisy[e]; i0 = e; }
        #pragma unroll
        for (int e = 0; e < NE; e++) if (e != i0 && noisy[e] > v1) { v1 = noisy[e]; i1 = e; }
        #pragma unroll
        for (int e = 0; e < NE; e++) if (e != i0 && e != i1 && noisy[e] > v2) v2 = noisy[e];

        float d = expf(v1 - v0);
        float g0 = 1.f / (1.f + d);
        float g1 = d / (1.f + d);

        g_topidx[2*t]   = i0;  g_topidx[2*t+1] = i1;
        g_gatesv[2*t]   = g0;  g_gatesv[2*t+1] = g1;
        atomicAdd(&g_counts[i0], 1);
        atomicAdd(&g_counts[i1], 1);

        #pragma unroll
        for (int e = 0; e < NE; e++) {
            bool is_in = noisy[e] > v2;
            float thr  = is_in ? v2 : v1;
            float p = normcdff((clean[e] - thr) / stdv[e]);
            g_load_part[e*NT + t] = p;
            g_imp_part[e*NT + t]  = (e == i0) ? g0 : ((e == i1) ? g1 : 0.f);
        }
    }
}

// ---------------- meta: 128-row tiles ----------------
__global__ void meta_kernel() {
    if (threadIdx.x != 0 || blockIdx.x != 0) return;
    int off = 0;
    for (int e = 0; e < NE; e++) { g_offsets[e] = off; off += g_counts[e]; }
    g_offsets[NE] = off;
    int nt = 0;
    for (int e = 0; e < NE; e++) {
        int c = g_counts[e], base = g_offsets[e];
        for (int r = 0; r < c; r += 128) {
            g_tile_e[nt]  = e;
            g_tile_r0[nt] = base + r;
            g_tile_r1[nt] = base + ((r + 128 < c) ? (r + 128) : c);
            nt++;
        }
    }
    g_ntiles = nt;
}

// ---------------- scatter ----------------
__global__ void scatter_kernel() {
    int t = blockIdx.x * blockDim.x + threadIdx.x;
    if (t >= NT) return;
    #pragma unroll
    for (int j = 0; j < 2; j++) {
        int e = g_topidx[2*t + j];
        int p = atomicAdd(&g_cursor[e], 1);
        int row = g_offsets[e] + p;
        g_perm[row]    = t;
        g_rowgate[row] = g_gatesv[2*t + j];
        g_slot[2*t + j] = row;
    }
}

// ---------------- tf32 mma.sync grouped GEMM, natural-layout B ----------------
// CTA: 128 grouped rows x 128 cols. 8 warps 2(m) x 4(n), warp tile 64x32.
// K-chunk 16, 4-buffer cp.async pipeline (wait_group 2) -> 2 CTAs/SM (84KB).
// A: permuted-K scratch, LDS.64 fragments (RSA=24, conflict-free).
// B: ORIGINAL weights [K][N], LDS.32 fragments + cvt.rna at load (RSB=136, conflict-free).
#define RSA 24
#define RSB 136
#define AFL (128*RSA)                  // 3072 floats
#define BFL (16*RSB)                   // 2176 floats
#define STF (AFL+BFL)                  // 5248 floats / stage
#define NBUF 4
#define GEMM_SMEM (NBUF * STF * 4)     // 83968 bytes

template<bool FFN1>
__global__ void __launch_bounds__(256, 2)
mma_ffn_kernel(const float* __restrict__ W, const float* __restrict__ bias)
{
    constexpr int KTOT = FFN1 ? DM : DF;
    constexpr int NTOT = FFN1 ? DF : DM;
    constexpr int NS   = KTOT / 16;

    int tile = blockIdx.y;
    if (tile >= g_ntiles) return;
    const int e  = g_tile_e[tile];
    const int r0 = g_tile_r0[tile];
    const int r1 = g_tile_r1[tile];
    const int n0 = blockIdx.x * 128;

    const float* Abase = FFN1 ? g_Xr : g_H;
    float*       Out   = FFN1 ? g_H  : g_O;

    extern __shared__ float sm[];
    const uint32_t smb = smem_u32(sm);

    const int tid = threadIdx.x;
    const int wid = tid >> 5;
    const int lane = tid & 31;
    const int warp_m = wid >> 2;   // 0..1
    const int warp_n = wid & 3;    // 0..3
    const int lm = lane >> 2;      // 0..7
    const int lk = lane & 3;       // 0..3

    // 4 cp.async slots/thread: idx 0..511 -> A (128 rows x 4 chunks), 512..1023 -> B (16 rows x 32 chunks)
    const float* src[4]; uint32_t sz[4]; uint32_t dst[4]; int stp[4];
    #pragma unroll
    for (int i = 0; i < 4; i++) {
        int idx = tid + i * 256;
        if (idx < 512) {
            int row = idx >> 2, ch = idx & 3;
            int gr = r0 + row;
            bool v = gr < r1;
            size_t ar = FFN1 ? (v ? (size_t)g_perm[gr] : 0) : (v ? (size_t)gr : 0);
            src[i] = Abase + ar * KTOT + ch * 4;
            sz[i]  = v ? 16u : 0u;
            dst[i] = smb + (uint32_t)(row * RSA + ch * 4) * 4u;
            stp[i] = 16;
        } else {
            int j = idx - 512;
            int krow = j >> 5, ch = j & 31;
            src[i] = W + (size_t)e * KTOT * NTOT + (size_t)krow * NTOT + n0 + ch * 4;
            sz[i]  = 16u;
            dst[i] = smb + (uint32_t)(AFL + krow * RSB + ch * 4) * 4u;
            stp[i] = 16 * NTOT;
        }
    }

    float acc[4][4][4];
    #pragma unroll
    for (int a = 0; a < 4; a++)
        #pragma unroll
        for (int b = 0; b < 4; b++)
            #pragma unroll
            for (int c = 0; c < 4; c++) acc[a][b][c] = 0.f;

    // prefetch stages 0..2
    #pragma unroll
    for (int s = 0; s < 3; s++) {
        uint32_t so = (uint32_t)(s * STF * 4);
        #pragma unroll
        for (int i = 0; i < 4; i++) {
            asm volatile("cp.async.cg.shared.global [%0], [%1], 16, %2;"
                         :: "r"(dst[i] + so), "l"(src[i]), "r"(sz[i]) : "memory");
            src[i] += stp[i];
        }
        asm volatile("cp.async.commit_group;" ::: "memory");
    }

    for (int s = 0; s < NS; s++) {
        if (s < NS - 2)       asm volatile("cp.async.wait_group 2;" ::: "memory");
        else if (s == NS - 2) asm volatile("cp.async.wait_group 1;" ::: "memory");
        else                  asm volatile("cp.async.wait_group 0;" ::: "memory");
        __syncthreads();

        if (s + 3 < NS) {
            uint32_t so = (uint32_t)(((s + 3) & (NBUF - 1)) * STF * 4);
            #pragma unroll
            for (int i = 0; i < 4; i++) {
                asm volatile("cp.async.cg.shared.global [%0], [%1], 16, %2;"
                             :: "r"(dst[i] + so), "l"(src[i]), "r"(sz[i]) : "memory");
                src[i] += stp[i];
            }
            asm volatile("cp.async.commit_group;" ::: "memory");
        }

        const float* A = sm + (s & (NBUF - 1)) * STF;
        const float* B = A + AFL;

        #pragma unroll
        for (int kk = 0; kk < 2; kk++) {
            const int k8 = kk * 8 + 2 * lk;        // permuted A offset
            const int kb = kk * 8 + lk;            // natural B k-row
            uint32_t af[4][4], bf[4][2];
            #pragma unroll
            for (int mt = 0; mt < 4; mt++) {
                int r = warp_m * 64 + mt * 16 + lm;
                float2 p0 = *(const float2*)(A + r * RSA + k8);
                float2 p1 = *(const float2*)(A + (r + 8) * RSA + k8);
                af[mt][0] = __float_as_uint(p0.x);   // (r,   k+lk)
                af[mt][2] = __float_as_uint(p0.y);   // (r,   k+lk+4)
                af[mt][1] = __float_as_uint(p1.x);   // (r+8, k+lk)
                af[mt][3] = __float_as_uint(p1.y);   // (r+8, k+lk+4)
            }
            #pragma unroll
            for (int nt = 0; nt < 4; nt++) {
                int c = warp_n * 32 + nt * 8 + lm;
                bf[nt][0] = rna_tf32_u(B[kb * RSB + c]);
                bf[nt][1] = rna_tf32_u(B[(kb + 4) * RSB + c]);
            }
            #pragma unroll
            for (int mt = 0; mt < 4; mt++)
                #pragma unroll
                for (int nt = 0; nt < 4; nt++)
                    mma_tf32(acc[mt][nt], af[mt][0], af[mt][1], af[mt][2], af[mt][3],
                             bf[nt][0], bf[nt][1]);
        }
    }

    // ---- epilogue ----
    #pragma unroll
    for (int mt = 0; mt < 4; mt++) {
        #pragma unroll
        for (int nt = 0; nt < 4; nt++) {
            int c0 = n0 + warp_n * 32 + nt * 8 + 2 * lk;
            float b0 = bias[(size_t)e * NTOT + c0];
            float b1 = bias[(size_t)e * NTOT + c0 + 1];
            #pragma unroll
            for (int h = 0; h < 2; h++) {
                int row = warp_m * 64 + mt * 16 + lm + h * 8;
                int gr = r0 + row;
                if (gr >= r1) continue;
                float v0 = acc[mt][nt][2*h + 0] + b0;
                float v1 = acc[mt][nt][2*h + 1] + b1;
                float* o = Out + (size_t)gr * NTOT;
                if (FFN1) {
                    // H feeds FFN2's K dimension -> store K-permuted, tf32-rounded
                    o[permk(c0)]     = rna_tf32(fmaxf(v0, 0.f));
                    o[permk(c0 + 1)] = rna_tf32(fmaxf(v1, 0.f));
                } else {
                    float gate = g_rowgate[gr];
                    o[c0]     = v0 * gate;
                    o[c0 + 1] = v1 * gate;
                }
            }
        }
    }
}

// ---------------- combine ----------------
__global__ void combine_kernel(float* __restrict__ out) {
    int idx = blockIdx.x * blockDim.x + threadIdx.x;
    int t = idx >> 10;
    int n = idx & 1023;
    float v = g_O[(size_t)g_slot[2*t]   * DM + n]
            + g_O[(size_t)g_slot[2*t+1] * DM + n];
    if (v == 0.0f) v = 2.2204460492503131e-16f;
    out[idx] = v;
}

// ---------------- loss ----------------
__global__ void reduce_kernel() {
    int e = blockIdx.x;
    __shared__ float sl[256], si[256];
    float a = 0.f, b = 0.f;
    for (int i = threadIdx.x; i < NT; i += 256) {
        a += g_load_part[e*NT + i];
        b += g_imp_part[e*NT + i];
    }
    sl[threadIdx.x] = a; si[threadIdx.x] = b;
    __syncthreads();
    for (int s = 128; s > 0; s >>= 1) {
        if (threadIdx.x < s) {
            sl[threadIdx.x] += sl[threadIdx.x + s];
            si[threadIdx.x] += si[threadIdx.x + s];
        }
        __syncthreads();
    }
    if (threadIdx.x == 0) { g_loadsum[e] = sl[0]; g_impsum[e] = si[0]; }
}

__global__ void loss_kernel(float* __restrict__ out, int out_size) {
    if (threadIdx.x != 0 || blockIdx.x != 0) return;
    float mi = 0.f, ml = 0.f;
    for (int e = 0; e < NE; e++) { mi += g_impsum[e]; ml += g_loadsum[e]; }
    mi *= (1.f / NE); ml *= (1.f / NE);
    float vi = 0.f, vl = 0.f;
    for (int e = 0; e < NE; e++) {
        float di = g_impsum[e] - mi; vi += di * di;
        float dl = g_loadsum[e] - ml; vl += dl * dl;
    }
    vi /= (float)(NE - 1);
    vl /= (float)(NE - 1);
    float loss = 0.1f * (vi / (mi*mi + 1e-10f) + vl / (ml*ml + 1e-10f));
    out[out_size - 1] = loss;
}

// ---------------- launch ----------------
extern "C" void kernel_launch(void* const* d_in, const int* in_sizes, int n_in,
                              void* d_out, int out_size) {
    const float* x     = (const float*)d_in[0];
    const float* noise = (const float*)d_in[1];
    const float* wg    = (const float*)d_in[2];
    const float* wn    = (const float*)d_in[3];
    const float* w1    = (const float*)d_in[4];
    const float* b1    = (const float*)d_in[5];
    const float* w2    = (const float*)d_in[6];
    const float* b2    = (const float*)d_in[7];
    float* out = (float*)d_out;

    cudaFuncSetAttribute(mma_ffn_kernel<true>,
                         cudaFuncAttributeMaxDynamicSharedMemorySize, GEMM_SMEM);
    cudaFuncSetAttribute(mma_ffn_kernel<false>,
                         cudaFuncAttributeMaxDynamicSharedMemorySize, GEMM_SMEM);

    reset_kernel<<<1, 32>>>();
    gating_kernel<<<NT/4, 128>>>(x, noise, wg, wn);
    meta_kernel<<<1, 1>>>();
    scatter_kernel<<<NT/256, 256>>>();

    mma_ffn_kernel<true ><<<dim3(DF/128, TILEY), 256, GEMM_SMEM>>>(w1, b1);
    mma_ffn_kernel<false><<<dim3(DM/128, TILEY), 256, GEMM_SMEM>>>(w2, b2);

    combine_kernel<<<(NT*DM)/256, 256>>>(out);
    reduce_kernel<<<NE, 256>>>();
    loss_kernel<<<1, 32>>>(out, out_size);
}

// round 7
// speedup vs baseline: 1.0550x; 1.0550x over previous
#include <cuda_runtime.h>
#include <math.h>
#include <math_constants.h>
#include <stdint.h>

#define NT 4096
#define DM 1024
#define DF 2048
#define NE 8
#define MAXROWS (2*NT)
#define MAXTILES 80
#define TILEY 72

// ---------------- static device scratch ----------------
__device__ int   g_counts[NE];
__device__ int   g_cursor[NE];
__device__ int   g_offsets[NE+1];
__device__ int   g_perm[MAXROWS];
__device__ float g_rowgate[MAXROWS];
__device__ int   g_slot[MAXROWS];
__device__ int   g_topidx[MAXROWS];
__device__ float g_gatesv[MAXROWS];
__device__ float g_imp_part[NE*NT];
__device__ float g_load_part[NE*NT];
__device__ float g_impsum[NE];
__device__ float g_loadsum[NE];
__device__ int   g_tile_e[MAXTILES];
__device__ int   g_tile_r0[MAXTILES];
__device__ int   g_tile_r1[MAXTILES];
__device__ int   g_ntiles;
__device__ int   g_done[MAXTILES];                 // FFN1 col-tiles completed per row-tile
__device__ float g_H[(size_t)MAXROWS * DF];        // K-permuted tf32 activations
__device__ float g_O[(size_t)MAXROWS * DM];        // natural layout
__device__ float g_Xr[(size_t)NT * DM];            // K-permuted tf32 x
__device__ float g_w1t[(size_t)NE * DF * DM];      // [E][N=DF][K=DM] K-permuted tf32
__device__ float g_w2t[(size_t)NE * DM * DF];      // [E][N=DM][K=DF] K-permuted tf32

// ---------------- helpers ----------------
__device__ __forceinline__ uint32_t smem_u32(const void* p) {
    uint32_t r;
    asm("{ .reg .u64 t; cvta.to.shared.u64 t, %1; cvt.u32.u64 %0, t; }" : "=r"(r) : "l"(p));
    return r;
}
__device__ __forceinline__ float rna_tf32(float v) {
    uint32_t u;
    asm("cvt.rna.tf32.f32 %0, %1;" : "=r"(u) : "f"(v));
    return __uint_as_float(u);
}
// within each 8-group, store K order [0,4,1,5,2,6,3,7]; fragment pairs (k, k+4) contiguous
__device__ __forceinline__ int permk(int k) {
    int j = k & 7;
    return (k & ~7) + ((j < 4) ? 2*j : 2*(j-4) + 1);
}
__device__ __forceinline__ void mma_tf32(float* c, uint32_t a0, uint32_t a1,
                                         uint32_t a2, uint32_t a3,
                                         uint32_t b0, uint32_t b1) {
    asm volatile("mma.sync.aligned.m16n8k8.row.col.f32.tf32.tf32.f32 "
        "{%0,%1,%2,%3}, {%4,%5,%6,%7}, {%8,%9}, {%0,%1,%2,%3};"
        : "+f"(c[0]), "+f"(c[1]), "+f"(c[2]), "+f"(c[3])
        : "r"(a0), "r"(a1), "r"(a2), "r"(a3), "r"(b0), "r"(b1));
}

// ---------------- reset ----------------
__global__ void reset_kernel() {
    int i = threadIdx.x;
    if (i < NE) { g_counts[i] = 0; g_cursor[i] = 0; }
    if (i < MAXTILES) g_done[i] = 0;
}

// ---------------- gating: one warp per token; also emits K-permuted tf32 x ----------------
__global__ void gating_kernel(const float* __restrict__ x,
                              const float* __restrict__ noise,
                              const float* __restrict__ wg,
                              const float* __restrict__ wn)
{
    int warp = (blockIdx.x * blockDim.x + threadIdx.x) >> 5;
    int lane = threadIdx.x & 31;
    if (warp >= NT) return;
    const int t = warp;

    float cg[NE], ng[NE];
    #pragma unroll
    for (int e = 0; e < NE; e++) { cg[e] = 0.f; ng[e] = 0.f; }

    const float* xr = x + (size_t)t * DM;
    float* xo = g_Xr + (size_t)t * DM;
    for (int k = lane; k < DM; k += 32) {
        float xv = xr[k];
        xo[permk(k)] = rna_tf32(xv);
        const float4* wg4 = (const float4*)(wg + (size_t)k * NE);
        const float4* wn4 = (const float4*)(wn + (size_t)k * NE);
        float4 a = wg4[0], b = wg4[1];
        float4 c = wn4[0], d = wn4[1];
        cg[0] = fmaf(xv, a.x, cg[0]); cg[1] = fmaf(xv, a.y, cg[1]);
        cg[2] = fmaf(xv, a.z, cg[2]); cg[3] = fmaf(xv, a.w, cg[3]);
        cg[4] = fmaf(xv, b.x, cg[4]); cg[5] = fmaf(xv, b.y, cg[5]);
        cg[6] = fmaf(xv, b.z, cg[6]); cg[7] = fmaf(xv, b.w, cg[7]);
        ng[0] = fmaf(xv, c.x, ng[0]); ng[1] = fmaf(xv, c.y, ng[1]);
        ng[2] = fmaf(xv, c.z, ng[2]); ng[3] = fmaf(xv, c.w, ng[3]);
        ng[4] = fmaf(xv, d.x, ng[4]); ng[5] = fmaf(xv, d.y, ng[5]);
        ng[6] = fmaf(xv, d.z, ng[6]); ng[7] = fmaf(xv, d.w, ng[7]);
    }
    #pragma unroll
    for (int e = 0; e < NE; e++) {
        #pragma unroll
        for (int o = 16; o > 0; o >>= 1) {
            cg[e] += __shfl_xor_sync(0xFFFFFFFFu, cg[e], o);
            ng[e] += __shfl_xor_sync(0xFFFFFFFFu, ng[e], o);
        }
    }

    if (lane == 0) {
        float clean[NE], stdv[NE], noisy[NE];
        #pragma unroll
        for (int e = 0; e < NE; e++) {
            clean[e] = cg[e];
            float v = ng[e];
            float sp = fmaxf(v, 0.f) + log1pf(expf(-fabsf(v)));
            stdv[e]  = sp + 0.01f;
            noisy[e] = clean[e] + noise[(size_t)t * NE + e] * stdv[e];
        }
        int i0 = 0, i1 = -1;
        float v0 = -CUDART_INF_F, v1 = -CUDART_INF_F, v2 = -CUDART_INF_F;
        #pragma unroll
        for (int e = 0; e < NE; e++) if (noisy[e] > v0) { v0 = noisy[e]; i0 = e; }
        #pragma unroll
        for (int e = 0; e < NE; e++) if (e != i0 && noisy[e] > v1) { v1 = noisy[e]; i1 = e; }
        #pragma unroll
        for (int e = 0; e < NE; e++) if (e != i0 && e != i1 && noisy[e] > v2) v2 = noisy[e];

        float d = expf(v1 - v0);
        float g0 = 1.f / (1.f + d);
        float g1 = d / (1.f + d);

        g_topidx[2*t]   = i0;  g_topidx[2*t+1] = i1;
        g_gatesv[2*t]   = g0;  g_gatesv[2*t+1] = g1;
        atomicAdd(&g_counts[i0], 1);
        atomicAdd(&g_counts[i1], 1);

        #pragma unroll
        for (int e = 0; e < NE; e++) {
            bool is_in = noisy[e] > v2;
            float thr  = is_in ? v2 : v1;
            float p = normcdff((clean[e] - thr) / stdv[e]);
            g_load_part[e*NT + t] = p;
            g_imp_part[e*NT + t]  = (e == i0) ? g0 : ((e == i1) ? g1 : 0.f);
        }
    }
}

// ---------------- meta: 128-row tiles ----------------
__global__ void meta_kernel() {
    if (threadIdx.x != 0 || blockIdx.x != 0) return;
    int off = 0;
    for (int e = 0; e < NE; e++) { g_offsets[e] = off; off += g_counts[e]; }
    g_offsets[NE] = off;
    int nt = 0;
    for (int e = 0; e < NE; e++) {
        int c = g_counts[e], base = g_offsets[e];
        for (int r = 0; r < c; r += 128) {
            g_tile_e[nt]  = e;
            g_tile_r0[nt] = base + r;
            g_tile_r1[nt] = base + ((r + 128 < c) ? (r + 128) : c);
            nt++;
        }
    }
    g_ntiles = nt;
}

// ---------------- scatter ----------------
__global__ void scatter_kernel() {
    int t = blockIdx.x * blockDim.x + threadIdx.x;
    if (t >= NT) return;
    #pragma unroll
    for (int j = 0; j < 2; j++) {
        int e = g_topidx[2*t + j];
        int p = atomicAdd(&g_cursor[e], 1);
        int row = g_offsets[e] + p;
        g_perm[row]    = t;
        g_rowgate[row] = g_gatesv[2*t + j];
        g_slot[2*t + j] = row;
    }
}

// ---------------- weight transpose + tf32 round + K-permute (both weights) ----------------
// W[e][K][N] (N contiguous) -> Wt[e][N][K-permuted].  blockIdx.z: 0..7 -> w1, 8..15 -> w2.
__global__ void transpose_round_kernel(const float* __restrict__ W1,
                                       const float* __restrict__ W2)
{
    __shared__ float t[32][33];
    bool one = blockIdx.z < 8;
    int e = one ? blockIdx.z : (blockIdx.z - 8);
    const int K = one ? DM : DF;
    const int N = one ? DF : DM;
    const float* Wp = (one ? W1 : W2) + (size_t)e * K * N;
    float* Wo = (one ? g_w1t : g_w2t) + (size_t)e * K * N;
    // grid x covers max(DF,DM)/32 = 64; clamp for the smaller dim
    int nblk = N / 32, kblk_max = K / 32;
    int n0 = (blockIdx.x % nblk) * 32;
    int k0 = (blockIdx.y % kblk_max) * 32;
    if (blockIdx.x >= (unsigned)nblk || blockIdx.y >= (unsigned)kblk_max) return;
    int tx = threadIdx.x, ty = threadIdx.y;
    #pragma unroll
    for (int i = 0; i < 32; i += 8)
        t[ty + i][tx] = Wp[(size_t)(k0 + ty + i) * N + n0 + tx];
    __syncthreads();
    #pragma unroll
    for (int i = 0; i < 32; i += 8)
        Wo[(size_t)(n0 + ty + i) * K + permk(k0 + tx)] = rna_tf32(t[tx][ty + i]);
}

// ---------------- fused tf32 mma.sync grouped GEMM (FFN1 then FFN2 in one launch) ----------
// CTA: 128 grouped rows x 128 cols. 8 warps 2(m) x 4(n), warp tile 64x32.
// 2-stage double buffer (80KB -> 2 CTAs/SM), K-chunk 32/stage. RS=40 pad.
// Blocks [0, 16*TILEY): FFN1.  Blocks [16*TILEY, 24*TILEY): FFN2, spin on g_done[tile]==16.
#define RS 40
#define AST (128*RS)
#define STF (2*AST)                    // 10240 floats / stage
#define GEMM_SMEM (2 * STF * 4)        // 81920 bytes
#define FFN1_BLOCKS (16*TILEY)
#define FFN_BLOCKS  (24*TILEY)

template<bool FFN1>
__device__ __forceinline__ void gemm_body(int tile, int n0, const float* __restrict__ bias,
                                          float* sm, uint32_t smb)
{
    constexpr int KTOT = FFN1 ? DM : DF;
    constexpr int NTOT = FFN1 ? DF : DM;
    constexpr int NS   = KTOT / 32;

    const int e  = g_tile_e[tile];
    const int r0 = g_tile_r0[tile];
    const int r1 = g_tile_r1[tile];

    const float* Abase = FFN1 ? g_Xr : g_H;
    const float* Wt    = FFN1 ? g_w1t : g_w2t;
    float*       Out   = FFN1 ? g_H  : g_O;

    const int tid = threadIdx.x;
    const int wid = tid >> 5;
    const int lane = tid & 31;
    const int warp_m = wid >> 2;   // 0..1
    const int warp_n = wid & 3;    // 0..3
    const int lm = lane >> 2;      // 0..7
    const int lk = lane & 3;       // 0..3

    // 8 cp.async slots/thread: 0..3 -> A (1024 16B chunks), 4..7 -> B (1024)
    const float* src[8]; uint32_t sz[8]; uint32_t dst[8];
    #pragma unroll
    for (int i = 0; i < 8; i++) {
        int idx = tid + i * 256;
        if (idx < 1024) {
            int row = idx >> 3, ch = idx & 7;
            int gr = r0 + row;
            bool v = gr < r1;
            size_t ar = FFN1 ? (v ? (size_t)g_perm[gr] : 0) : (v ? (size_t)gr : 0);
            src[i] = Abase + ar * KTOT + ch * 4;
            sz[i]  = v ? 16u : 0u;
            dst[i] = smb + (uint32_t)(row * RS + ch * 4) * 4u;
        } else {
            int j = idx - 1024;
            int row = j >> 3, ch = j & 7;
            src[i] = Wt + ((size_t)e * NTOT + (size_t)(n0 + row)) * KTOT + ch * 4;
            sz[i]  = 16u;
            dst[i] = smb + (uint32_t)(AST + row * RS + ch * 4) * 4u;
        }
    }

    float acc[4][4][4];
    #pragma unroll
    for (int a = 0; a < 4; a++)
        #pragma unroll
        for (int b = 0; b < 4; b++)
            #pragma unroll
            for (int c = 0; c < 4; c++) acc[a][b][c] = 0.f;

    // prefetch stage 0
    #pragma unroll
    for (int i = 0; i < 8; i++)
        asm volatile("cp.async.cg.shared.global [%0], [%1], 16, %2;"
                     :: "r"(dst[i]), "l"(src[i]), "r"(sz[i]) : "memory");
    asm volatile("cp.async.commit_group;" ::: "memory");

    for (int s = 0; s < NS; s++) {
        asm volatile("cp.async.wait_group 0;" ::: "memory");
        __syncthreads();

        if (s + 1 < NS) {
            uint32_t so = (uint32_t)(((s + 1) & 1) * STF * 4);
            int k0 = (s + 1) * 32;
            #pragma unroll
            for (int i = 0; i < 8; i++)
                asm volatile("cp.async.cg.shared.global [%0], [%1], 16, %2;"
                             :: "r"(dst[i] + so), "l"(src[i] + k0), "r"(sz[i]) : "memory");
            asm volatile("cp.async.commit_group;" ::: "memory");
        }

        const float* A = sm + (s & 1) * STF;
        const float* B = A + AST;

        #pragma unroll
        for (int kk = 0; kk < 4; kk++) {
            const int k8 = kk * 8 + 2 * lk;
            uint32_t af[4][4], bf[4][2];
            #pragma unroll
            for (int mt = 0; mt < 4; mt++) {
                int r = warp_m * 64 + mt * 16 + lm;
                float2 p0 = *(const float2*)(A + r * RS + k8);
                float2 p1 = *(const float2*)(A + (r + 8) * RS + k8);
                af[mt][0] = __float_as_uint(p0.x);
                af[mt][2] = __float_as_uint(p0.y);
                af[mt][1] = __float_as_uint(p1.x);
                af[mt][3] = __float_as_uint(p1.y);
            }
            #pragma unroll
            for (int nt = 0; nt < 4; nt++) {
                int c = warp_n * 32 + nt * 8 + lm;
                float2 pb = *(const float2*)(B + c * RS + k8);
                bf[nt][0] = __float_as_uint(pb.x);
                bf[nt][1] = __float_as_uint(pb.y);
            }
            #pragma unroll
            for (int mt = 0; mt < 4; mt++)
                #pragma unroll
                for (int nt = 0; nt < 4; nt++)
                    mma_tf32(acc[mt][nt], af[mt][0], af[mt][1], af[mt][2], af[mt][3],
                             bf[nt][0], bf[nt][1]);
        }
    }

    // ---- epilogue ----
    #pragma unroll
    for (int mt = 0; mt < 4; mt++) {
        #pragma unroll
        for (int nt = 0; nt < 4; nt++) {
            int c0 = n0 + warp_n * 32 + nt * 8 + 2 * lk;
            float b0 = bias[(size_t)e * NTOT + c0];
            float b1 = bias[(size_t)e * NTOT + c0 + 1];
            #pragma unroll
            for (int h = 0; h < 2; h++) {
                int row = warp_m * 64 + mt * 16 + lm + h * 8;
                int gr = r0 + row;
                if (gr >= r1) continue;
                float v0 = acc[mt][nt][2*h + 0] + b0;
                float v1 = acc[mt][nt][2*h + 1] + b1;
                float* o = Out + (size_t)gr * NTOT;
                if (FFN1) {
                    o[permk(c0)]     = rna_tf32(fmaxf(v0, 0.f));
                    o[permk(c0 + 1)] = rna_tf32(fmaxf(v1, 0.f));
                } else {
                    float gate = g_rowgate[gr];
                    o[c0]     = v0 * gate;
                    o[c0 + 1] = v1 * gate;
                }
            }
        }
    }
}

__global__ void __launch_bounds__(256, 2)
ffn_fused_kernel(const float* __restrict__ w1t_bias, const float* __restrict__ b1,
                 const float* __restrict__ b2)
{
    extern __shared__ float sm[];
    const uint32_t smb = smem_u32(sm);
    int blk = blockIdx.x;

    if (blk < FFN1_BLOCKS) {
        int tile = blk >> 4;
        if (tile >= g_ntiles) return;
        int n0 = (blk & 15) * 128;
        gemm_body<true>(tile, n0, b1, sm, smb);
        __syncthreads();
        if (threadIdx.x == 0) {
            __threadfence();
            atomicAdd(&g_done[tile], 1);
        }
    } else {
        int j = blk - FFN1_BLOCKS;
        int tile = j >> 3;
        if (tile >= g_ntiles) return;
        int n0 = (j & 7) * 128;
        if (threadIdx.x == 0) {
            while (atomicAdd(&g_done[tile], 0) < 16) __nanosleep(128);
        }
        __syncthreads();
        __threadfence();
        gemm_body<false>(tile, n0, b2, sm, smb);
    }
}

// ---------------- combine ----------------
__global__ void combine_kernel(float* __restrict__ out) {
    int idx = blockIdx.x * blockDim.x + threadIdx.x;
    int t = idx >> 10;
    int n = idx & 1023;
    float v = g_O[(size_t)g_slot[2*t]   * DM + n]
            + g_O[(size_t)g_slot[2*t+1] * DM + n];
    if (v == 0.0f) v = 2.2204460492503131e-16f;
    out[idx] = v;
}

// ---------------- loss ----------------
__global__ void reduce_kernel() {
    int e = blockIdx.x;
    __shared__ float sl[256], si[256];
    float a = 0.f, b = 0.f;
    for (int i = threadIdx.x; i < NT; i += 256) {
        a += g_load_part[e*NT + i];
        b += g_imp_part[e*NT + i];
    }
    sl[threadIdx.x] = a; si[threadIdx.x] = b;
    __syncthreads();
    for (int s = 128; s > 0; s >>= 1) {
        if (threadIdx.x < s) {
            sl[threadIdx.x] += sl[threadIdx.x + s];
            si[threadIdx.x] += si[threadIdx.x + s];
        }
        __syncthreads();
    }
    if (threadIdx.x == 0) { g_loadsum[e] = sl[0]; g_impsum[e] = si[0]; }
}

__global__ void loss_kernel(float* __restrict__ out, int out_size) {
    if (threadIdx.x != 0 || blockIdx.x != 0) return;
    float mi = 0.f, ml = 0.f;
    for (int e = 0; e < NE; e++) { mi += g_impsum[e]; ml += g_loadsum[e]; }
    mi *= (1.f / NE); ml *= (1.f / NE);
    float vi = 0.f, vl = 0.f;
    for (int e = 0; e < NE; e++) {
        float di = g_impsum[e] - mi; vi += di * di;
        float dl = g_loadsum[e] - ml; vl += dl * dl;
    }
    vi /= (float)(NE - 1);
    vl /= (float)(NE - 1);
    float loss = 0.1f * (vi / (mi*mi + 1e-10f) + vl / (ml*ml + 1e-10f));
    out[out_size - 1] = loss;
}

// ---------------- launch ----------------
extern "C" void kernel_launch(void* const* d_in, const int* in_sizes, int n_in,
                              void* d_out, int out_size) {
    const float* x     = (const float*)d_in[0];
    const float* noise = (const float*)d_in[1];
    const float* wg    = (const float*)d_in[2];
    const float* wn    = (const float*)d_in[3];
    const float* w1    = (const float*)d_in[4];
    const float* b1    = (const float*)d_in[5];
    const float* w2    = (const float*)d_in[6];
    const float* b2    = (const float*)d_in[7];
    float* out = (float*)d_out;

    cudaFuncSetAttribute(ffn_fused_kernel,
                         cudaFuncAttributeMaxDynamicSharedMemorySize, GEMM_SMEM);

    reset_kernel<<<1, 128>>>();
    gating_kernel<<<NT/4, 128>>>(x, noise, wg, wn);
    meta_kernel<<<1, 1>>>();
    scatter_kernel<<<NT/256, 256>>>();

    // z: 0..7 -> w1 (N=2048 -> 64 nblk, K=1024 -> 32 kblk), 8..15 -> w2 (32 nblk, 64 kblk)
    transpose_round_kernel<<<dim3(64, 64, 16), dim3(32, 8)>>>(w1, w2);

    ffn_fused_kernel<<<FFN_BLOCKS, 256, GEMM_SMEM>>>(nullptr, b1, b2);

    combine_kernel<<<(NT*DM)/256, 256>>>(out);
    reduce_kernel<<<NE, 256>>>();
    loss_kernel<<<1, 32>>>(out, out_size);
}

// round 8
// speedup vs baseline: 1.7478x; 1.6567x over previous
#include <cuda_runtime.h>
#include <cuda_fp16.h>
#include <math.h>
#include <math_constants.h>
#include <stdint.h>

#define NT 4096
#define DM 1024
#define DF 2048
#define NE 8
#define MAXROWS (2*NT)
#define MAXTILES 80
#define TILEY 72

// ---------------- static device scratch ----------------
__device__ int   g_counts[NE];
__device__ int   g_cursor[NE];
__device__ int   g_offsets[NE+1];
__device__ int   g_perm[MAXROWS];
__device__ float g_rowgate[MAXROWS];
__device__ int   g_slot[MAXROWS];
__device__ int   g_topidx[MAXROWS];
__device__ float g_gatesv[MAXROWS];
__device__ float g_imp_part[NE*NT];
__device__ float g_load_part[NE*NT];
__device__ float g_impsum[NE];
__device__ float g_loadsum[NE];
__device__ int   g_tile_e[MAXTILES];
__device__ int   g_tile_r0[MAXTILES];
__device__ int   g_tile_r1[MAXTILES];
__device__ int   g_ntiles;
__device__ __half g_Xrh[(size_t)NT * DM];          // 8 MB,  K-perm16 fp16 x
__device__ __half g_Hh[(size_t)MAXROWS * DF];      // 32 MB, K-perm16 fp16 H
__device__ float  g_O[(size_t)MAXROWS * DM];       // 32 MB, natural fp32
__device__ __half g_w1th[(size_t)NE * DF * DM];    // 32 MB [E][N=DF][K=DM] perm16
__device__ __half g_w2th[(size_t)NE * DM * DF];    // 32 MB [E][N=DM][K=DF] perm16

// ---------------- helpers ----------------
__device__ __forceinline__ uint32_t smem_u32(const void* p) {
    uint32_t r;
    asm("{ .reg .u64 t; cvta.to.shared.u64 t, %1; cvt.u32.u64 %0, t; }" : "=r"(r) : "l"(p));
    return r;
}
// within each 16-group, memory order [0,1,8,9, 2,3,10,11, 4,5,12,13, 6,7,14,15]:
// lane lk's fp16 fragment halves (2lk,2lk+1,2lk+8,2lk+9) are 8 contiguous bytes.
__device__ __forceinline__ int permk16(int k) {
    int r = k & 15, m = r & 7, h = (r >> 3) & 1;
    return (k & ~15) + (m >> 1) * 4 + h * 2 + (m & 1);
}
__device__ __forceinline__ void mma_f16(float* c, uint32_t a0, uint32_t a1,
                                        uint32_t a2, uint32_t a3,
                                        uint32_t b0, uint32_t b1) {
    asm volatile("mma.sync.aligned.m16n8k16.row.col.f32.f16.f16.f32 "
        "{%0,%1,%2,%3}, {%4,%5,%6,%7}, {%8,%9}, {%0,%1,%2,%3};"
        : "+f"(c[0]), "+f"(c[1]), "+f"(c[2]), "+f"(c[3])
        : "r"(a0), "r"(a1), "r"(a2), "r"(a3), "r"(b0), "r"(b1));
}

// ---------------- reset ----------------
__global__ void reset_kernel() {
    int i = threadIdx.x;
    if (i < NE) { g_counts[i] = 0; g_cursor[i] = 0; }
}

// ---------------- gating: one warp per token; emits perm16 fp16 x ----------------
__global__ void gating_kernel(const float* __restrict__ x,
                              const float* __restrict__ noise,
                              const float* __restrict__ wg,
                              const float* __restrict__ wn)
{
    int warp = (blockIdx.x * blockDim.x + threadIdx.x) >> 5;
    int lane = threadIdx.x & 31;
    if (warp >= NT) return;
    const int t = warp;

    float cg[NE], ng[NE];
    #pragma unroll
    for (int e = 0; e < NE; e++) { cg[e] = 0.f; ng[e] = 0.f; }

    const float* xr = x + (size_t)t * DM;
    __half* xo = g_Xrh + (size_t)t * DM;
    for (int k = lane; k < DM; k += 32) {
        float xv = xr[k];
        xo[permk16(k)] = __float2half_rn(xv);
        const float4* wg4 = (const float4*)(wg + (size_t)k * NE);
        const float4* wn4 = (const float4*)(wn + (size_t)k * NE);
        float4 a = wg4[0], b = wg4[1];
        float4 c = wn4[0], d = wn4[1];
        cg[0] = fmaf(xv, a.x, cg[0]); cg[1] = fmaf(xv, a.y, cg[1]);
        cg[2] = fmaf(xv, a.z, cg[2]); cg[3] = fmaf(xv, a.w, cg[3]);
        cg[4] = fmaf(xv, b.x, cg[4]); cg[5] = fmaf(xv, b.y, cg[5]);
        cg[6] = fmaf(xv, b.z, cg[6]); cg[7] = fmaf(xv, b.w, cg[7]);
        ng[0] = fmaf(xv, c.x, ng[0]); ng[1] = fmaf(xv, c.y, ng[1]);
        ng[2] = fmaf(xv, c.z, ng[2]); ng[3] = fmaf(xv, c.w, ng[3]);
        ng[4] = fmaf(xv, d.x, ng[4]); ng[5] = fmaf(xv, d.y, ng[5]);
        ng[6] = fmaf(xv, d.z, ng[6]); ng[7] = fmaf(xv, d.w, ng[7]);
    }
    #pragma unroll
    for (int e = 0; e < NE; e++) {
        #pragma unroll
        for (int o = 16; o > 0; o >>= 1) {
            cg[e] += __shfl_xor_sync(0xFFFFFFFFu, cg[e], o);
            ng[e] += __shfl_xor_sync(0xFFFFFFFFu, ng[e], o);
        }
    }

    if (lane == 0) {
        float clean[NE], stdv[NE], noisy[NE];
        #pragma unroll
        for (int e = 0; e < NE; e++) {
            clean[e] = cg[e];
            float v = ng[e];
            float sp = fmaxf(v, 0.f) + log1pf(expf(-fabsf(v)));
            stdv[e]  = sp + 0.01f;
            noisy[e] = clean[e] + noise[(size_t)t * NE + e] * stdv[e];
        }
        int i0 = 0, i1 = -1;
        float v0 = -CUDART_INF_F, v1 = -CUDART_INF_F, v2 = -CUDART_INF_F;
        #pragma unroll
        for (int e = 0; e < NE; e++) if (noisy[e] > v0) { v0 = noisy[e]; i0 = e; }
        #pragma unroll
        for (int e = 0; e < NE; e++) if (e != i0 && noisy[e] > v1) { v1 = noisy[e]; i1 = e; }
        #pragma unroll
        for (int e = 0; e < NE; e++) if (e != i0 && e != i1 && noisy[e] > v2) v2 = noisy[e];

        float d = expf(v1 - v0);
        float g0 = 1.f / (1.f + d);
        float g1 = d / (1.f + d);

        g_topidx[2*t]   = i0;  g_topidx[2*t+1] = i1;
        g_gatesv[2*t]   = g0;  g_gatesv[2*t+1] = g1;
        atomicAdd(&g_counts[i0], 1);
        atomicAdd(&g_counts[i1], 1);

        #pragma unroll
        for (int e = 0; e < NE; e++) {
            bool is_in = noisy[e] > v2;
            float thr  = is_in ? v2 : v1;
            float p = normcdff((clean[e] - thr) / stdv[e]);
            g_load_part[e*NT + t] = p;
            g_imp_part[e*NT + t]  = (e == i0) ? g0 : ((e == i1) ? g1 : 0.f);
        }
    }
}

// ---------------- meta: 128-row tiles ----------------
__global__ void meta_kernel() {
    if (threadIdx.x != 0 || blockIdx.x != 0) return;
    int off = 0;
    for (int e = 0; e < NE; e++) { g_offsets[e] = off; off += g_counts[e]; }
    g_offsets[NE] = off;
    int nt = 0;
    for (int e = 0; e < NE; e++) {
        int c = g_counts[e], base = g_offsets[e];
        for (int r = 0; r < c; r += 128) {
            g_tile_e[nt]  = e;
            g_tile_r0[nt] = base + r;
            g_tile_r1[nt] = base + ((r + 128 < c) ? (r + 128) : c);
            nt++;
        }
    }
    g_ntiles = nt;
}

// ---------------- scatter ----------------
__global__ void scatter_kernel() {
    int t = blockIdx.x * blockDim.x + threadIdx.x;
    if (t >= NT) return;
    #pragma unroll
    for (int j = 0; j < 2; j++) {
        int e = g_topidx[2*t + j];
        int p = atomicAdd(&g_cursor[e], 1);
        int row = g_offsets[e] + p;
        g_perm[row]    = t;
        g_rowgate[row] = g_gatesv[2*t + j];
        g_slot[2*t + j] = row;
    }
}

// ---------------- weight transpose -> fp16 perm16 ----------------
// W[e][K][N] (N contiguous) -> Wt[e][N][K-perm16] as __half
template<bool ONE>
__global__ void transpose_h_kernel(const float* __restrict__ W) {
    constexpr int K = ONE ? DM : DF;
    constexpr int N = ONE ? DF : DM;
    __half* Wt = ONE ? g_w1th : g_w2th;
    __shared__ float t[32][33];
    int e = blockIdx.z;
    const float* Wp = W + (size_t)e * K * N;
    __half* Wo = Wt + (size_t)e * K * N;
    int n0 = blockIdx.x * 32, k0 = blockIdx.y * 32;
    int tx = threadIdx.x, ty = threadIdx.y;
    #pragma unroll
    for (int i = 0; i < 32; i += 8)
        t[ty + i][tx] = Wp[(size_t)(k0 + ty + i) * N + n0 + tx];
    __syncthreads();
    #pragma unroll
    for (int i = 0; i < 32; i += 8)
        Wo[(size_t)(n0 + ty + i) * K + permk16(k0 + tx)] = __float2half_rn(t[tx][ty + i]);
}

// ---------------- fp16 mma.sync grouped GEMM ----------------
// CTA: 128 grouped rows x 128 cols. 8 warps 2(m) x 4(n), warp tile 64x32.
// 2-stage double buffer, K-chunk 64 halves/stage. RSH=80 halves (160B) row pad:
// fragment LDS.64 conflict-free (row stride 40 words == 8 mod 32).
#define RSH 80
#define ASTH (128*RSH)                 // halves per A stage block
#define STFH (2*ASTH)                  // halves per stage (A+B)
#define GEMM_SMEM (2 * STFH * 2)       // 81920 bytes

template<bool FFN1>
__global__ void __launch_bounds__(256, 2)
mma_ffn_kernel(const float* __restrict__ bias)
{
    constexpr int KTOT = FFN1 ? DM : DF;
    constexpr int NTOT = FFN1 ? DF : DM;
    constexpr int NS   = KTOT / 64;

    int tile = blockIdx.y;
    if (tile >= g_ntiles) return;
    const int e  = g_tile_e[tile];
    const int r0 = g_tile_r0[tile];
    const int r1 = g_tile_r1[tile];
    const int n0 = blockIdx.x * 128;

    const __half* Abase = FFN1 ? g_Xrh : g_Hh;
    const __half* Wt    = FFN1 ? g_w1th : g_w2th;

    extern __shared__ __half smh[];
    const uint32_t smb = smem_u32(smh);

    const int tid = threadIdx.x;
    const int wid = tid >> 5;
    const int lane = tid & 31;
    const int warp_m = wid >> 2;   // 0..1
    const int warp_n = wid & 3;    // 0..3
    const int lm = lane >> 2;      // 0..7
    const int lk = lane & 3;       // 0..3

    // 8 cp.async slots/thread: stage = 128 A-rows x 128B + 128 B-rows x 128B
    // idx 0..1023 -> A (row = idx>>3, ch = idx&7), 1024..2047 -> B
    const __half* src[8]; uint32_t sz[8]; uint32_t dst[8];
    #pragma unroll
    for (int i = 0; i < 8; i++) {
        int idx = tid + i * 256;
        if (idx < 1024) {
            int row = idx >> 3, ch = idx & 7;
            int gr = r0 + row;
            bool v = gr < r1;
            size_t ar = FFN1 ? (v ? (size_t)g_perm[gr] : 0) : (v ? (size_t)gr : 0);
            src[i] = Abase + ar * KTOT + ch * 8;
            sz[i]  = v ? 16u : 0u;
            dst[i] = smb + (uint32_t)(row * RSH + ch * 8) * 2u;
        } else {
            int j = idx - 1024;
            int row = j >> 3, ch = j & 7;
            src[i] = Wt + ((size_t)e * NTOT + (size_t)(n0 + row)) * KTOT + ch * 8;
            sz[i]  = 16u;
            dst[i] = smb + (uint32_t)(ASTH + row * RSH + ch * 8) * 2u;
        }
    }

    float acc[4][4][4];
    #pragma unroll
    for (int a = 0; a < 4; a++)
        #pragma unroll
        for (int b = 0; b < 4; b++)
            #pragma unroll
            for (int c = 0; c < 4; c++) acc[a][b][c] = 0.f;

    // prefetch stage 0
    #pragma unroll
    for (int i = 0; i < 8; i++)
        asm volatile("cp.async.cg.shared.global [%0], [%1], 16, %2;"
                     :: "r"(dst[i]), "l"(src[i]), "r"(sz[i]) : "memory");
    asm volatile("cp.async.commit_group;" ::: "memory");

    for (int s = 0; s < NS; s++) {
        asm volatile("cp.async.wait_group 0;" ::: "memory");
        __syncthreads();

        if (s + 1 < NS) {
            uint32_t so = (uint32_t)(((s + 1) & 1) * STFH * 2);
            int k0 = (s + 1) * 64;
            #pragma unroll
            for (int i = 0; i < 8; i++)
                asm volatile("cp.async.cg.shared.global [%0], [%1], 16, %2;"
                             :: "r"(dst[i] + so), "l"(src[i] + k0), "r"(sz[i]) : "memory");
            asm volatile("cp.async.commit_group;" ::: "memory");
        }

        const __half* A = smh + (s & 1) * STFH;
        const __half* B = A + ASTH;

        #pragma unroll
        for (int kk = 0; kk < 4; kk++) {
            const int ko = kk * 16 + lk * 4;   // perm16: lane's 4 halves contiguous
            uint32_t af[4][4], bf[4][2];
            #pragma unroll
            for (int mt = 0; mt < 4; mt++) {
                int r = warp_m * 64 + mt * 16 + lm;
                uint2 p0 = *(const uint2*)(A + r * RSH + ko);        // a0 (k,k+1), a2 (k+8,k+9)
                uint2 p1 = *(const uint2*)(A + (r + 8) * RSH + ko);  // a1, a3
                af[mt][0] = p0.x; af[mt][2] = p0.y;
                af[mt][1] = p1.x; af[mt][3] = p1.y;
            }
            #pragma unroll
            for (int nt = 0; nt < 4; nt++) {
                int c = warp_n * 32 + nt * 8 + lm;
                uint2 pb = *(const uint2*)(B + c * RSH + ko);        // b0, b1
                bf[nt][0] = pb.x; bf[nt][1] = pb.y;
            }
            #pragma unroll
            for (int mt = 0; mt < 4; mt++)
                #pragma unroll
                for (int nt = 0; nt < 4; nt++)
                    mma_f16(acc[mt][nt], af[mt][0], af[mt][1], af[mt][2], af[mt][3],
                            bf[nt][0], bf[nt][1]);
        }
    }

    // ---- epilogue ----
    #pragma unroll
    for (int mt = 0; mt < 4; mt++) {
        #pragma unroll
        for (int nt = 0; nt < 4; nt++) {
            int c0 = n0 + warp_n * 32 + nt * 8 + 2 * lk;   // even
            float b0 = bias[(size_t)e * NTOT + c0];
            float b1 = bias[(size_t)e * NTOT + c0 + 1];
            #pragma unroll
            for (int h = 0; h < 2; h++) {
                int row = warp_m * 64 + mt * 16 + lm + h * 8;
                int gr = r0 + row;
                if (gr >= r1) continue;
                float v0 = acc[mt][nt][2*h + 0] + b0;
                float v1 = acc[mt][nt][2*h + 1] + b1;
                if (FFN1) {
                    // H feeds FFN2's K dim -> store perm16 fp16 pair
                    int m = c0 & 7, hb = (c0 >> 3) & 1;
                    int pos = (c0 & ~15) + (m >> 1) * 4 + hb * 2;
                    __half2 hv = __floats2half2_rn(fmaxf(v0, 0.f), fmaxf(v1, 0.f));
                    *(__half2*)(g_Hh + (size_t)gr * DF + pos) = hv;
                } else {
                    float gate = g_rowgate[gr];
                    float* o = g_O + (size_t)gr * DM;
                    o[c0]     = v0 * gate;
                    o[c0 + 1] = v1 * gate;
                }
            }
        }
    }
}

// ---------------- combine ----------------
__global__ void combine_kernel(float* __restrict__ out) {
    int idx = blockIdx.x * blockDim.x + threadIdx.x;
    int t = idx >> 10;
    int n = idx & 1023;
    float v = g_O[(size_t)g_slot[2*t]   * DM + n]
            + g_O[(size_t)g_slot[2*t+1] * DM + n];
    if (v == 0.0f) v = 2.2204460492503131e-16f;
    out[idx] = v;
}

// ---------------- loss ----------------
__global__ void reduce_kernel() {
    int e = blockIdx.x;
    __shared__ float sl[256], si[256];
    float a = 0.f, b = 0.f;
    for (int i = threadIdx.x; i < NT; i += 256) {
        a += g_load_part[e*NT + i];
        b += g_imp_part[e*NT + i];
    }
    sl[threadIdx.x] = a; si[threadIdx.x] = b;
    __syncthreads();
    for (int s = 128; s > 0; s >>= 1) {
        if (threadIdx.x < s) {
            sl[threadIdx.x] += sl[threadIdx.x + s];
            si[threadIdx.x] += si[threadIdx.x + s];
        }
        __syncthreads();
    }
    if (threadIdx.x == 0) { g_loadsum[e] = sl[0]; g_impsum[e] = si[0]; }
}

__global__ void loss_kernel(float* __restrict__ out, int out_size) {
    if (threadIdx.x != 0 || blockIdx.x != 0) return;
    float mi = 0.f, ml = 0.f;
    for (int e = 0; e < NE; e++) { mi += g_impsum[e]; ml += g_loadsum[e]; }
    mi *= (1.f / NE); ml *= (1.f / NE);
    float vi = 0.f, vl = 0.f;
    for (int e = 0; e < NE; e++) {
        float di = g_impsum[e] - mi; vi += di * di;
        float dl = g_loadsum[e] - ml; vl += dl * dl;
    }
    vi /= (float)(NE - 1);
    vl /= (float)(NE - 1);
    float loss = 0.1f * (vi / (mi*mi + 1e-10f) + vl / (ml*ml + 1e-10f));
    out[out_size - 1] = loss;
}

// ---------------- launch ----------------
extern "C" void kernel_launch(void* const* d_in, const int* in_sizes, int n_in,
                              void* d_out, int out_size) {
    const float* x     = (const float*)d_in[0];
    const float* noise = (const float*)d_in[1];
    const float* wg    = (const float*)d_in[2];
    const float* wn    = (const float*)d_in[3];
    const float* w1    = (const float*)d_in[4];
    const float* b1    = (const float*)d_in[5];
    const float* w2    = (const float*)d_in[6];
    const float* b2    = (const float*)d_in[7];
    float* out = (float*)d_out;

    cudaFuncSetAttribute(mma_ffn_kernel<true>,
                         cudaFuncAttributeMaxDynamicSharedMemorySize, GEMM_SMEM);
    cudaFuncSetAttribute(mma_ffn_kernel<false>,
                         cudaFuncAttributeMaxDynamicSharedMemorySize, GEMM_SMEM);

    reset_kernel<<<1, 32>>>();
    gating_kernel<<<NT/4, 128>>>(x, noise, wg, wn);
    meta_kernel<<<1, 1>>>();
    scatter_kernel<<<NT/256, 256>>>();

    transpose_h_kernel<true ><<<dim3(DF/32, DM/32, NE), dim3(32, 8)>>>(w1);
    transpose_h_kernel<false><<<dim3(DM/32, DF/32, NE), dim3(32, 8)>>>(w2);

    mma_ffn_kernel<true ><<<dim3(DF/128, TILEY), 256, GEMM_SMEM>>>(b1);
    mma_ffn_kernel<false><<<dim3(DM/128, TILEY), 256, GEMM_SMEM>>>(b2);

    combine_kernel<<<(NT*DM)/256, 256>>>(out);
    reduce_kernel<<<NE, 256>>>();
    loss_kernel<<<1, 32>>>(out, out_size);
}